// round 3
// baseline (speedup 1.0000x reference)
#include <cuda_runtime.h>
#include <math.h>

#define BB 8
#define TT 16384
#define RC 32
#define CLS 256
#define ECH 256
#define NL 40
#define DILATION 1024
#define BT (BB*TT)

// -------- scratch (device globals; no allocation allowed) --------
__device__ float g_h[BB*RC*TT];      // residual stream  (16 MB)
__device__ float g_skip[BB*RC*TT];   // skip accumulator (16 MB)
__device__ float g_u[BB*RC*TT];      // pre-BN residual conv out (16 MB)
__device__ float g_y[BB*ECH*TT];     // e1 output (128 MB)
__device__ float g_stats[512];       // per-channel sum / sumsq
__device__ float g_ab[512];          // per-channel scale / shift

__device__ __forceinline__ float sigmoidf_(float x){ return 1.f/(1.f+expf(-x)); }
__device__ __forceinline__ float mishf_(float x){
    float sp = (x > 20.f) ? x : log1pf(expf(x));
    return x * tanhf(sp);
}

// ================= start conv: h = W(32x256) @ shift1(x) + b; skip = 0 =================
__global__ void __launch_bounds__(256) k_start(const float* __restrict__ x,
                                               const float* __restrict__ sw,
                                               const float* __restrict__ sb){
    __shared__ float sX[32*128];
    __shared__ float sW[32*32];
    int tid = threadIdx.x, blk = blockIdx.x;
    int b = blk >> 7;            // grid = 8 * 128
    int t0 = (blk & 127) << 7;
    if (blk == 0 && tid < 512 && tid < 512) { if (tid < 512) g_stats[tid] = 0.f; }
    int og = tid >> 6, tj = tid & 63;
    float a0[8], a1[8];
    #pragma unroll
    for (int i = 0; i < 8; i++){ a0[i]=0.f; a1[i]=0.f; }

    for (int ch = 0; ch < 8; ch++){
        int base = ch*32;
        #pragma unroll
        for (int i = 0; i < 16; i++){
            int e = tid + i*256;
            int cc = e >> 7, j = e & 127;
            int gt = t0 + j - 1;
            sX[e] = (gt >= 0) ? x[((size_t)(b*CLS + base + cc))*TT + gt] : 0.f;
        }
        #pragma unroll
        for (int i = 0; i < 4; i++){
            int e = tid + i*256;
            int k = e >> 5, o = e & 31;
            sW[e] = sw[o*CLS + base + k];   // sW[k][o]
        }
        __syncthreads();
        #pragma unroll 8
        for (int k = 0; k < 32; k++){
            float2 in = *(const float2*)(sX + k*128 + 2*tj);
            float w[8];
            *(float4*)&w[0] = *(const float4*)(sW + k*32 + 8*og);
            *(float4*)&w[4] = *(const float4*)(sW + k*32 + 8*og + 4);
            #pragma unroll
            for (int u = 0; u < 8; u++){
                a0[u] = fmaf(w[u], in.x, a0[u]);
                a1[u] = fmaf(w[u], in.y, a1[u]);
            }
        }
        __syncthreads();
    }
    int t = t0 + 2*tj;
    #pragma unroll
    for (int i = 0; i < 8; i++){
        int c = 8*og + i;
        size_t idx = ((size_t)(b*RC + c))*TT + t;
        float bias = sb[c];
        *(float2*)&g_h[idx]    = make_float2(a0[i]+bias, a1[i]+bias);
        *(float2*)&g_skip[idx] = make_float2(0.f, 0.f);
    }
}

// ================= layer kernel A: gates + skip + residual conv + BN stats =================
__global__ void __launch_bounds__(256) k_layerA(
    const float* __restrict__ gtw, const float* __restrict__ gtb,
    const float* __restrict__ gsw, const float* __restrict__ gsb,
    const float* __restrict__ rw,  const float* __restrict__ rb)
{
    extern __shared__ float smem[];
    float* sIn  = smem;            // 64 x 128 (rows 0-31: h[t], rows 32-63: h[t-1024])
    float* sW   = smem + 8192;     // 64 x 64  transposed combined gate weights: sW[k*64+u], u=2c+s
    float* sRW  = smem + 12288;    // 32 x 32  transposed residual weights: sRW[c*32+o]
    float* sRed = smem + 13312;    // 64 reduction bins

    int tid = threadIdx.x, blk = blockIdx.x;
    int b = blk >> 7;
    int t0 = (blk & 127) << 7;
    int og = tid >> 6, tj = tid & 63;
    bool valid = (t0 >= DILATION);

    #pragma unroll
    for (int i = 0; i < 32; i++){
        int e = tid + i*256;
        int r = e >> 7, j = e & 127;
        float v;
        if (r < 32) v = g_h[((size_t)(b*RC + r))*TT + t0 + j];
        else        v = valid ? g_h[((size_t)(b*RC + (r-32)))*TT + t0 - DILATION + j] : 0.f;
        sIn[e] = v;
    }
    #pragma unroll
    for (int i = 0; i < 16; i++){
        int e = tid + i*256;
        int k = e >> 6, u = e & 63;
        int c = u >> 1, s = u & 1;
        int tap = (k < 32) ? 1 : 0;
        int kk = k & 31;
        const float* wsrc = s ? gsw : gtw;
        sW[e] = wsrc[(c*32 + kk)*2 + tap];
    }
    #pragma unroll
    for (int i = 0; i < 4; i++){
        int e = tid + i*256;
        int c = e >> 5, o = e & 31;
        sRW[e] = rw[o*32 + c];
    }
    if (tid < 64) sRed[tid] = 0.f;
    __syncthreads();

    float a0[16], a1[16];
    #pragma unroll
    for (int u = 0; u < 16; u++){ a0[u]=0.f; a1[u]=0.f; }
    const float* wbase = sW + 16*og;
    #pragma unroll 8
    for (int k = 0; k < 64; k++){
        float2 in = *(const float2*)(sIn + k*128 + 2*tj);
        float w[16];
        *(float4*)&w[0]  = *(const float4*)(wbase + k*64);
        *(float4*)&w[4]  = *(const float4*)(wbase + k*64 + 4);
        *(float4*)&w[8]  = *(const float4*)(wbase + k*64 + 8);
        *(float4*)&w[12] = *(const float4*)(wbase + k*64 + 12);
        #pragma unroll
        for (int u = 0; u < 16; u++){
            a0[u] = fmaf(w[u], in.x, a0[u]);
            a1[u] = fmaf(w[u], in.y, a1[u]);
        }
    }
    __syncthreads();

    int t = t0 + 2*tj;
    #pragma unroll
    for (int i = 0; i < 8; i++){
        int c = 8*og + i;
        float tb = gtb[c], sb2 = gsb[c];
        float gv0 = tanhf(a0[2*i] + tb) * sigmoidf_(a0[2*i+1] + sb2);
        float gv1 = tanhf(a1[2*i] + tb) * sigmoidf_(a1[2*i+1] + sb2);
        size_t idx = ((size_t)(b*RC + c))*TT + t;
        float2 sk = *(float2*)&g_skip[idx];
        sk.x += gv0; sk.y += gv1;
        *(float2*)&g_skip[idx] = sk;
        sIn[c*128 + 2*tj]     = gv0;   // reuse sIn as g-tile
        sIn[c*128 + 2*tj + 1] = gv1;
    }
    __syncthreads();

    float r0[8], r1[8];
    #pragma unroll
    for (int i = 0; i < 8; i++){ r0[i]=0.f; r1[i]=0.f; }
    #pragma unroll 8
    for (int c = 0; c < 32; c++){
        float2 gg = *(const float2*)(sIn + c*128 + 2*tj);
        float w[8];
        *(float4*)&w[0] = *(const float4*)(sRW + c*32 + 8*og);
        *(float4*)&w[4] = *(const float4*)(sRW + c*32 + 8*og + 4);
        #pragma unroll
        for (int i = 0; i < 8; i++){
            r0[i] = fmaf(w[i], gg.x, r0[i]);
            r1[i] = fmaf(w[i], gg.y, r1[i]);
        }
    }
    int lane = tid & 31;
    #pragma unroll
    for (int i = 0; i < 8; i++){
        int o = 8*og + i;
        float bias = rb[o];
        float u0 = r0[i] + bias, u1 = r1[i] + bias;
        size_t idx = ((size_t)(b*RC + o))*TT + t;
        *(float2*)&g_u[idx] = make_float2(u0, u1);
        float s = u0 + u1;
        float q = u0*u0 + u1*u1;
        #pragma unroll
        for (int off = 16; off > 0; off >>= 1){
            s += __shfl_down_sync(0xffffffffu, s, off);
            q += __shfl_down_sync(0xffffffffu, q, off);
        }
        if (lane == 0){
            atomicAdd(&sRed[o],      s);
            atomicAdd(&sRed[32 + o], q);
        }
    }
    __syncthreads();
    if (tid < 32){
        atomicAdd(&g_stats[tid],       sRed[tid]);
        atomicAdd(&g_stats[256 + tid], sRed[32 + tid]);
    }
}

// ================= finalize BN stats -> scale/shift, then zero stats =================
__global__ void k_finalize(int nch, const float* __restrict__ gamma, const float* __restrict__ beta){
    int tid = threadIdx.x;  // blockDim = 512
    if (tid < nch){
        float s = g_stats[tid], q = g_stats[256 + tid];
        float m = s * (1.f/(float)BT);
        float v = q * (1.f/(float)BT) - m*m;
        float a = gamma[tid] * rsqrtf(v + 1e-5f);
        g_ab[tid]       = a;
        g_ab[256 + tid] = beta[tid] - m*a;
    }
    __syncthreads();
    g_stats[tid] = 0.f;
}

// ================= apply BN: h += a[c]*u + b[c] =================
__global__ void __launch_bounds__(256) k_apply(){
    const float4* u4 = (const float4*)g_u;
    float4* h4 = (float4*)g_h;
    const int n4 = BB*RC*TT/4;
    for (int i = blockIdx.x*blockDim.x + threadIdx.x; i < n4; i += gridDim.x*blockDim.x){
        int c = (i >> 12) & 31;               // T/4 = 4096 float4 per (b,c)
        float a = g_ab[c], bsh = g_ab[256 + c];
        float4 u = u4[i], h = h4[i];
        h.x += fmaf(a, u.x, bsh);
        h.y += fmaf(a, u.y, bsh);
        h.z += fmaf(a, u.z, bsh);
        h.w += fmaf(a, u.w, bsh);
        h4[i] = h;
    }
}

// ================= stats of skip (for bn1) =================
__global__ void __launch_bounds__(256) k_skipstats(){
    __shared__ float sred[16];
    int blk = blockIdx.x;                 // grid = 256 rows * 8 chunks = 2048
    int row = blk >> 3;
    int chunk = blk & 7;
    int c = row & 31;
    const float4* p = (const float4*)(g_skip + (size_t)row*TT + chunk*2048);
    float s = 0.f, q = 0.f;
    int tid = threadIdx.x;
    for (int i = tid; i < 512; i += 256){
        float4 v = p[i];
        s += v.x+v.y+v.z+v.w;
        q += v.x*v.x+v.y*v.y+v.z*v.z+v.w*v.w;
    }
    #pragma unroll
    for (int off = 16; off > 0; off >>= 1){
        s += __shfl_down_sync(0xffffffffu, s, off);
        q += __shfl_down_sync(0xffffffffu, q, off);
    }
    int lane = tid & 31, w = tid >> 5;
    if (lane == 0){ sred[w] = s; sred[8 + w] = q; }
    __syncthreads();
    if (tid == 0){
        float S = 0.f, Q = 0.f;
        #pragma unroll
        for (int ww = 0; ww < 8; ww++){ S += sred[ww]; Q += sred[8 + ww]; }
        atomicAdd(&g_stats[c],       S);
        atomicAdd(&g_stats[256 + c], Q);
    }
}

// ================= e1: y = W1(256x32) @ mish(bn1(skip)) + b1, accumulate bn2 stats =================
__global__ void __launch_bounds__(256) k_e1(const float* __restrict__ w1, const float* __restrict__ b1){
    __shared__ float sM[32*64];
    __shared__ float sWT[32*256];
    __shared__ float sRed[512];
    int tid = threadIdx.x, blk = blockIdx.x;
    int b = blk >> 8;               // grid = 8 * 256
    int t0 = (blk & 255) << 6;
    #pragma unroll
    for (int i = 0; i < 32; i++){
        int e = tid + i*256;
        int k = e >> 8, o = e & 255;
        sWT[e] = w1[o*32 + k];
    }
    #pragma unroll
    for (int i = 0; i < 8; i++){
        int e = tid + i*256;
        int c = e >> 6, j = e & 63;
        float v = g_skip[((size_t)(b*RC + c))*TT + t0 + j];
        sM[e] = mishf_(fmaf(g_ab[c], v, g_ab[256 + c]));
    }
    sRed[tid] = 0.f; sRed[256 + tid] = 0.f;
    __syncthreads();

    int og = tid >> 4, tp = tid & 15;
    float4 acc[16];
    #pragma unroll
    for (int u = 0; u < 16; u++) acc[u] = make_float4(0.f,0.f,0.f,0.f);
    #pragma unroll 4
    for (int k = 0; k < 32; k++){
        float4 in = *(const float4*)(sM + k*64 + 4*tp);
        float w[16];
        *(float4*)&w[0]  = *(const float4*)(sWT + k*256 + 16*og);
        *(float4*)&w[4]  = *(const float4*)(sWT + k*256 + 16*og + 4);
        *(float4*)&w[8]  = *(const float4*)(sWT + k*256 + 16*og + 8);
        *(float4*)&w[12] = *(const float4*)(sWT + k*256 + 16*og + 12);
        #pragma unroll
        for (int u = 0; u < 16; u++){
            acc[u].x = fmaf(w[u], in.x, acc[u].x);
            acc[u].y = fmaf(w[u], in.y, acc[u].y);
            acc[u].z = fmaf(w[u], in.z, acc[u].z);
            acc[u].w = fmaf(w[u], in.w, acc[u].w);
        }
    }
    int lane16 = tid & 15;
    #pragma unroll
    for (int u = 0; u < 16; u++){
        int o = 16*og + u;
        float bias = b1[o];
        float4 v = acc[u];
        v.x += bias; v.y += bias; v.z += bias; v.w += bias;
        *(float4*)&g_y[((size_t)(b*ECH + o))*TT + t0 + 4*tp] = v;
        float s = v.x+v.y+v.z+v.w;
        float q = v.x*v.x+v.y*v.y+v.z*v.z+v.w*v.w;
        #pragma unroll
        for (int off = 8; off > 0; off >>= 1){
            s += __shfl_xor_sync(0xffffffffu, s, off);
            q += __shfl_xor_sync(0xffffffffu, q, off);
        }
        if (lane16 == 0){
            atomicAdd(&sRed[o],       s);
            atomicAdd(&sRed[256 + o], q);
        }
    }
    __syncthreads();
    atomicAdd(&g_stats[tid],       sRed[tid]);
    atomicAdd(&g_stats[256 + tid], sRed[256 + tid]);
}

// ================= e2: out = W2(256x256) @ mish(bn2(y)) + b2 =================
__global__ void __launch_bounds__(256) k_e2(const float* __restrict__ w2, const float* __restrict__ b2,
                                            float* __restrict__ out){
    extern __shared__ float smem2[];
    float* sM2 = smem2;            // 256 x 64
    float* sWT = smem2 + 16384;    // 32 x 256 weight chunk
    int tid = threadIdx.x, blk = blockIdx.x;
    int b = blk >> 8;
    int t0 = (blk & 255) << 6;
    #pragma unroll 8
    for (int i = 0; i < 64; i++){
        int e = tid + i*256;
        int c = e >> 6, j = e & 63;
        float v = g_y[((size_t)(b*ECH + c))*TT + t0 + j];
        sM2[e] = mishf_(fmaf(g_ab[c], v, g_ab[256 + c]));
    }
    int og = tid >> 4, tp = tid & 15;
    float4 acc[16];
    #pragma unroll
    for (int u = 0; u < 16; u++) acc[u] = make_float4(0.f,0.f,0.f,0.f);

    for (int kc = 0; kc < 8; kc++){
        __syncthreads();
        #pragma unroll
        for (int i = 0; i < 32; i++){
            int e = tid + i*256;
            int k = e >> 8, o = e & 255;
            sWT[e] = w2[o*256 + kc*32 + k];
        }
        __syncthreads();
        #pragma unroll 4
        for (int k = 0; k < 32; k++){
            float4 in = *(const float4*)(sM2 + (kc*32 + k)*64 + 4*tp);
            float w[16];
            *(float4*)&w[0]  = *(const float4*)(sWT + k*256 + 16*og);
            *(float4*)&w[4]  = *(const float4*)(sWT + k*256 + 16*og + 4);
            *(float4*)&w[8]  = *(const float4*)(sWT + k*256 + 16*og + 8);
            *(float4*)&w[12] = *(const float4*)(sWT + k*256 + 16*og + 12);
            #pragma unroll
            for (int u = 0; u < 16; u++){
                acc[u].x = fmaf(w[u], in.x, acc[u].x);
                acc[u].y = fmaf(w[u], in.y, acc[u].y);
                acc[u].z = fmaf(w[u], in.z, acc[u].z);
                acc[u].w = fmaf(w[u], in.w, acc[u].w);
            }
        }
    }
    #pragma unroll
    for (int u = 0; u < 16; u++){
        int o = 16*og + u;
        float bias = b2[o];
        float4 v = acc[u];
        v.x += bias; v.y += bias; v.z += bias; v.w += bias;
        *(float4*)&out[((size_t)(b*CLS + o))*TT + t0 + 4*tp] = v;
    }
}

// ================= launch =================
extern "C" void kernel_launch(void* const* d_in, const int* in_sizes, int n_in,
                              void* d_out, int out_size){
    const float* x       = (const float*)d_in[0];
    const float* start_w = (const float*)d_in[1];
    const float* start_b = (const float*)d_in[2];
    const float* gt_w    = (const float*)d_in[3];
    const float* gt_b    = (const float*)d_in[4];
    const float* gs_w    = (const float*)d_in[5];
    const float* gs_b    = (const float*)d_in[6];
    const float* res_w   = (const float*)d_in[7];
    const float* res_b   = (const float*)d_in[8];
    const float* bn_g    = (const float*)d_in[9];
    const float* bn_b    = (const float*)d_in[10];
    const float* bn1_g   = (const float*)d_in[11];
    const float* bn1_b   = (const float*)d_in[12];
    const float* e1_w    = (const float*)d_in[13];
    const float* e1_b    = (const float*)d_in[14];
    const float* bn2_g   = (const float*)d_in[15];
    const float* bn2_b   = (const float*)d_in[16];
    const float* e2_w    = (const float*)d_in[17];
    const float* e2_b    = (const float*)d_in[18];
    float* out = (float*)d_out;

    static bool attr_done = false;
    cudaFuncSetAttribute(k_layerA, cudaFuncAttributeMaxDynamicSharedMemorySize, 13376*4);
    cudaFuncSetAttribute(k_e2,     cudaFuncAttributeMaxDynamicSharedMemorySize, 24576*4);
    (void)attr_done;

    k_start<<<BB*(TT/128), 256>>>(x, start_w, start_b);

    for (int L = 0; L < NL; L++){
        k_layerA<<<BB*(TT/128), 256, 13376*4>>>(
            gt_w + (size_t)L*RC*RC*2, gt_b + L*RC,
            gs_w + (size_t)L*RC*RC*2, gs_b + L*RC,
            res_w + (size_t)L*RC*RC,  res_b + L*RC);
        k_finalize<<<1, 512>>>(RC, bn_g + L*RC, bn_b + L*RC);
        k_apply<<<2048, 256>>>();
    }

    k_skipstats<<<2048, 256>>>();
    k_finalize<<<1, 512>>>(RC, bn1_g, bn1_b);
    k_e1<<<BB*(TT/64), 256>>>(e1_w, e1_b);
    k_finalize<<<1, 512>>>(ECH, bn2_g, bn2_b);
    k_e2<<<BB*(TT/64), 256, 24576*4>>>(e2_w, e2_b, out);
}

// round 4
// speedup vs baseline: 1.2056x; 1.2056x over previous
#include <cuda_runtime.h>
#include <math.h>

#define BB 8
#define TT 16384
#define RC 32
#define CLS 256
#define ECH 256
#define NL 40
#define DILATION 1024
#define BT (BB*TT)
#define SLOT_BN1 39

// -------- scratch (device globals; no allocation allowed) --------
__device__ float g_hA[BB*RC*TT];     // residual stream buffer A (16 MB)
__device__ float g_hB[BB*RC*TT];     // residual stream buffer B (16 MB)
__device__ float g_uA[BB*RC*TT];     // pre-BN residual conv out, even layers
__device__ float g_uB[BB*RC*TT];     // pre-BN residual conv out, odd layers
__device__ float g_skip[BB*RC*TT];   // skip accumulator (16 MB)
__device__ float g_y[BB*ECH*TT];     // e1 output (128 MB)
__device__ float g_stats2[41*64];    // per-layer per-channel sum/sumsq (slot 39 = bn1)
__device__ float g_stats_e[512];     // bn2 stats (256 sum + 256 sumsq)

__device__ __forceinline__ float fast_tanh(float x){
    float e = __expf(fminf(2.f*x, 30.f));
    return __fdividef(e - 1.f, e + 1.f);
}
__device__ __forceinline__ float fast_sig(float x){
    return __fdividef(1.f, 1.f + __expf(fminf(-x, 30.f)));
}
__device__ __forceinline__ float fast_mish(float x){
    float e = __expf(fminf(x, 15.f));
    float p = 1.f + e;
    float p2 = p*p;
    float r = __fdividef(p2 - 1.f, p2 + 1.f);
    return (x > 15.f) ? x : x*r;
}

// ================= start conv: hA = W(32x256) @ shift1(x) + b; skip = 0; zero stats =================
__global__ void __launch_bounds__(256) k_start(const float* __restrict__ x,
                                               const float* __restrict__ sw,
                                               const float* __restrict__ sb){
    __shared__ float sX[32*128];
    __shared__ float sW[32*32];
    int tid = threadIdx.x, blk = blockIdx.x;
    int b = blk >> 7;            // grid = 8 * 128
    int t0 = (blk & 127) << 7;
    if (blk == 0){
        for (int i = tid; i < 41*64; i += 256) g_stats2[i] = 0.f;
        for (int i = tid; i < 512;  i += 256) g_stats_e[i] = 0.f;
    }
    int og = tid >> 6, tj = tid & 63;
    float a0[8], a1[8];
    #pragma unroll
    for (int i = 0; i < 8; i++){ a0[i]=0.f; a1[i]=0.f; }

    for (int ch = 0; ch < 8; ch++){
        int base = ch*32;
        #pragma unroll
        for (int i = 0; i < 16; i++){
            int e = tid + i*256;
            int cc = e >> 7, j = e & 127;
            int gt = t0 + j - 1;
            sX[e] = (gt >= 0) ? x[((size_t)(b*CLS + base + cc))*TT + gt] : 0.f;
        }
        #pragma unroll
        for (int i = 0; i < 4; i++){
            int e = tid + i*256;
            int k = e >> 5, o = e & 31;
            sW[e] = sw[o*CLS + base + k];   // sW[k][o]
        }
        __syncthreads();
        #pragma unroll 8
        for (int k = 0; k < 32; k++){
            float2 in = *(const float2*)(sX + k*128 + 2*tj);
            float w[8];
            *(float4*)&w[0] = *(const float4*)(sW + k*32 + 8*og);
            *(float4*)&w[4] = *(const float4*)(sW + k*32 + 8*og + 4);
            #pragma unroll
            for (int u = 0; u < 8; u++){
                a0[u] = fmaf(w[u], in.x, a0[u]);
                a1[u] = fmaf(w[u], in.y, a1[u]);
            }
        }
        __syncthreads();
    }
    int t = t0 + 2*tj;
    #pragma unroll
    for (int i = 0; i < 8; i++){
        int c = 8*og + i;
        size_t idx = ((size_t)(b*RC + c))*TT + t;
        float bias = sb[c];
        *(float2*)&g_hA[idx]   = make_float2(a0[i]+bias, a1[i]+bias);
        *(float2*)&g_skip[idx] = make_float2(0.f, 0.f);
    }
}

// ================= fused layer kernel: bn-apply(prev) + gates + skip + res conv + stats =================
__global__ void __launch_bounds__(256, 4) k_layer(
    int L,
    const float* __restrict__ gtw, const float* __restrict__ gtb,
    const float* __restrict__ gsw, const float* __restrict__ gsb,
    const float* __restrict__ rw,  const float* __restrict__ rb,
    const float* __restrict__ gprev, const float* __restrict__ bprev)
{
    extern __shared__ float smem[];
    float* sIn  = smem;            // 64 x 128
    float* sW   = smem + 8192;     // 64 x 64 combined gate weights (transposed)
    float* sRW  = smem + 12288;    // 32 x 32 residual weights (transposed)
    float* sRed = smem + 13312;    // 64 reduction bins
    float* sAB  = smem + 13376;    // 64: prev-layer BN scale/shift

    const bool first = (L == 0);
    const bool last  = (L == NL-1);
    const float* hIn  = (first || (L & 1)) ? g_hA : g_hB;
    float*       hOut = (L & 1) ? g_hB : g_hA;
    const float* uIn  = (L & 1) ? g_uA : g_uB;
    float*       uOut = (L & 1) ? g_uB : g_uA;
    const bool wH = (L >= 1) && !last;

    int tid = threadIdx.x, blk = blockIdx.x;
    int b = blk >> 7;
    int t0 = (blk & 127) << 7;
    int og = tid >> 6, tj = tid & 63;
    int lane = tid & 31;

    // prev-layer BN coefficients (redundant per block, trivially cheap)
    if (tid < 32){
        float a = 0.f, sh = 0.f;
        if (!first){
            float s = g_stats2[(L-1)*64 + tid];
            float q = g_stats2[(L-1)*64 + 32 + tid];
            float m = s * (1.f/(float)BT);
            float v = q * (1.f/(float)BT) - m*m;
            a  = gprev[tid] * rsqrtf(v + 1e-5f);
            sh = bprev[tid] - m*a;
        }
        sAB[tid] = a; sAB[32+tid] = sh;
    }
    // gate weights: sW[k*64 + u], u = 2c + s; k<32 -> tap1 (current), k>=32 -> tap0 (dilated)
    #pragma unroll
    for (int i = 0; i < 16; i++){
        int e = tid + i*256;
        int k = e >> 6, u = e & 63;
        int c = u >> 1, s = u & 1;
        int tap = (k < 32) ? 1 : 0;
        int kk = k & 31;
        const float* wsrc = s ? gsw : gtw;
        sW[e] = wsrc[(c*32 + kk)*2 + tap];
    }
    #pragma unroll
    for (int i = 0; i < 4; i++){
        int e = tid + i*256;
        sRW[e] = rw[(e & 31)*32 + (e >> 5)];   // sRW[c*32+o] = rw[o*32+c]
    }
    if (tid < 64) sRed[tid] = 0.f;
    __syncthreads();

    // staging with fused BN-apply of previous layer; write reconstructed h for current rows
    bool dvalid = (t0 >= DILATION);
    #pragma unroll
    for (int i = 0; i < 8; i++){
        int e = tid + i*256;            // float4 index within 64x128 tile
        int r = e >> 5, j4 = e & 31;
        float4 v = make_float4(0.f,0.f,0.f,0.f);
        if (r < 32 || dvalid){
            int c = (r < 32) ? r : r - 32;
            size_t off = ((size_t)(b*RC + c))*TT + ((r < 32) ? t0 : t0 - DILATION) + 4*j4;
            v = *(const float4*)&hIn[off];
            if (!first){
                float a = sAB[c], sh = sAB[32+c];
                float4 u = *(const float4*)&uIn[off];
                v.x = fmaf(a, u.x, v.x) + sh;
                v.y = fmaf(a, u.y, v.y) + sh;
                v.z = fmaf(a, u.z, v.z) + sh;
                v.w = fmaf(a, u.w, v.w) + sh;
            }
            if (r < 32 && wH) *(float4*)&hOut[off] = v;
        }
        ((float4*)sIn)[e] = v;
    }
    __syncthreads();

    // gate GEMM: 64 k x 16 outputs x 2 timesteps per thread
    float a0[16], a1[16];
    #pragma unroll
    for (int u = 0; u < 16; u++){ a0[u]=0.f; a1[u]=0.f; }
    const float* wbase = sW + 16*og;
    #pragma unroll 8
    for (int k = 0; k < 64; k++){
        float2 in = *(const float2*)(sIn + k*128 + 2*tj);
        #pragma unroll
        for (int part = 0; part < 4; part++){
            float4 w = *(const float4*)(wbase + k*64 + 4*part);
            a0[4*part+0] = fmaf(w.x, in.x, a0[4*part+0]);
            a0[4*part+1] = fmaf(w.y, in.x, a0[4*part+1]);
            a0[4*part+2] = fmaf(w.z, in.x, a0[4*part+2]);
            a0[4*part+3] = fmaf(w.w, in.x, a0[4*part+3]);
            a1[4*part+0] = fmaf(w.x, in.y, a1[4*part+0]);
            a1[4*part+1] = fmaf(w.y, in.y, a1[4*part+1]);
            a1[4*part+2] = fmaf(w.z, in.y, a1[4*part+2]);
            a1[4*part+3] = fmaf(w.w, in.y, a1[4*part+3]);
        }
    }
    __syncthreads();

    int t = t0 + 2*tj;
    #pragma unroll
    for (int i = 0; i < 8; i++){
        int c = 8*og + i;
        float tb = gtb[c], sb2 = gsb[c];
        float gv0 = fast_tanh(a0[2*i] + tb) * fast_sig(a0[2*i+1] + sb2);
        float gv1 = fast_tanh(a1[2*i] + tb) * fast_sig(a1[2*i+1] + sb2);
        size_t idx = ((size_t)(b*RC + c))*TT + t;
        float2 sk = *(float2*)&g_skip[idx];
        sk.x += gv0; sk.y += gv1;
        *(float2*)&g_skip[idx] = sk;
        if (!last){
            sIn[c*128 + 2*tj]     = gv0;
            sIn[c*128 + 2*tj + 1] = gv1;
        } else {
            // final skip stats (bn1)
            float s = sk.x + sk.y;
            float q = sk.x*sk.x + sk.y*sk.y;
            #pragma unroll
            for (int off = 16; off > 0; off >>= 1){
                s += __shfl_down_sync(0xffffffffu, s, off);
                q += __shfl_down_sync(0xffffffffu, q, off);
            }
            if (lane == 0){
                atomicAdd(&sRed[c],      s);
                atomicAdd(&sRed[32 + c], q);
            }
        }
    }
    if (last){
        __syncthreads();
        if (tid < 64) atomicAdd(&g_stats2[SLOT_BN1*64 + tid], sRed[tid]);
        return;
    }
    __syncthreads();

    // residual conv
    float r0[8], r1[8];
    #pragma unroll
    for (int i = 0; i < 8; i++){ r0[i]=0.f; r1[i]=0.f; }
    #pragma unroll 8
    for (int c = 0; c < 32; c++){
        float2 gg = *(const float2*)(sIn + c*128 + 2*tj);
        float w[8];
        *(float4*)&w[0] = *(const float4*)(sRW + c*32 + 8*og);
        *(float4*)&w[4] = *(const float4*)(sRW + c*32 + 8*og + 4);
        #pragma unroll
        for (int i = 0; i < 8; i++){
            r0[i] = fmaf(w[i], gg.x, r0[i]);
            r1[i] = fmaf(w[i], gg.y, r1[i]);
        }
    }
    #pragma unroll
    for (int i = 0; i < 8; i++){
        int o = 8*og + i;
        float bias = rb[o];
        float u0 = r0[i] + bias, u1 = r1[i] + bias;
        size_t idx = ((size_t)(b*RC + o))*TT + t;
        *(float2*)&uOut[idx] = make_float2(u0, u1);
        float s = u0 + u1;
        float q = u0*u0 + u1*u1;
        #pragma unroll
        for (int off = 16; off > 0; off >>= 1){
            s += __shfl_down_sync(0xffffffffu, s, off);
            q += __shfl_down_sync(0xffffffffu, q, off);
        }
        if (lane == 0){
            atomicAdd(&sRed[o],      s);
            atomicAdd(&sRed[32 + o], q);
        }
    }
    __syncthreads();
    if (tid < 64) atomicAdd(&g_stats2[L*64 + tid], sRed[tid]);
}

// ================= e1: y = W1(256x32) @ mish(bn1(skip)) + b1, accumulate bn2 stats =================
__global__ void __launch_bounds__(256) k_e1(const float* __restrict__ w1, const float* __restrict__ b1,
                                            const float* __restrict__ bn1g, const float* __restrict__ bn1b){
    __shared__ float sM[32*64];
    __shared__ float sWT[32*256];
    __shared__ float sRed[512];
    __shared__ float sAB[64];
    int tid = threadIdx.x, blk = blockIdx.x;
    int b = blk >> 8;               // grid = 8 * 256
    int t0 = (blk & 255) << 6;
    if (tid < 32){
        float s = g_stats2[SLOT_BN1*64 + tid];
        float q = g_stats2[SLOT_BN1*64 + 32 + tid];
        float m = s * (1.f/(float)BT);
        float v = q * (1.f/(float)BT) - m*m;
        float a = bn1g[tid] * rsqrtf(v + 1e-5f);
        sAB[tid] = a; sAB[32+tid] = bn1b[tid] - m*a;
    }
    #pragma unroll
    for (int i = 0; i < 32; i++){
        int e = tid + i*256;
        int k = e >> 8, o = e & 255;
        sWT[e] = w1[o*32 + k];
    }
    sRed[tid] = 0.f; sRed[256 + tid] = 0.f;
    __syncthreads();
    #pragma unroll
    for (int i = 0; i < 2; i++){
        int e = tid + i*256;            // float4 idx in 32x64 tile
        int c = e >> 4, j4 = e & 15;
        float4 v = *(const float4*)&g_skip[((size_t)(b*RC + c))*TT + t0 + 4*j4];
        float a = sAB[c], sh = sAB[32+c];
        v.x = fast_mish(fmaf(a, v.x, sh));
        v.y = fast_mish(fmaf(a, v.y, sh));
        v.z = fast_mish(fmaf(a, v.z, sh));
        v.w = fast_mish(fmaf(a, v.w, sh));
        ((float4*)sM)[e] = v;
    }
    __syncthreads();

    int og = tid >> 4, tp = tid & 15;
    float4 acc[16];
    #pragma unroll
    for (int u = 0; u < 16; u++) acc[u] = make_float4(0.f,0.f,0.f,0.f);
    #pragma unroll 4
    for (int k = 0; k < 32; k++){
        float4 in = *(const float4*)(sM + k*64 + 4*tp);
        float w[16];
        *(float4*)&w[0]  = *(const float4*)(sWT + k*256 + 16*og);
        *(float4*)&w[4]  = *(const float4*)(sWT + k*256 + 16*og + 4);
        *(float4*)&w[8]  = *(const float4*)(sWT + k*256 + 16*og + 8);
        *(float4*)&w[12] = *(const float4*)(sWT + k*256 + 16*og + 12);
        #pragma unroll
        for (int u = 0; u < 16; u++){
            acc[u].x = fmaf(w[u], in.x, acc[u].x);
            acc[u].y = fmaf(w[u], in.y, acc[u].y);
            acc[u].z = fmaf(w[u], in.z, acc[u].z);
            acc[u].w = fmaf(w[u], in.w, acc[u].w);
        }
    }
    int lane16 = tid & 15;
    #pragma unroll
    for (int u = 0; u < 16; u++){
        int o = 16*og + u;
        float bias = b1[o];
        float4 v = acc[u];
        v.x += bias; v.y += bias; v.z += bias; v.w += bias;
        *(float4*)&g_y[((size_t)(b*ECH + o))*TT + t0 + 4*tp] = v;
        float s = v.x+v.y+v.z+v.w;
        float q = v.x*v.x+v.y*v.y+v.z*v.z+v.w*v.w;
        #pragma unroll
        for (int off = 8; off > 0; off >>= 1){
            s += __shfl_xor_sync(0xffffffffu, s, off);
            q += __shfl_xor_sync(0xffffffffu, q, off);
        }
        if (lane16 == 0){
            atomicAdd(&sRed[o],       s);
            atomicAdd(&sRed[256 + o], q);
        }
    }
    __syncthreads();
    atomicAdd(&g_stats_e[tid],       sRed[tid]);
    atomicAdd(&g_stats_e[256 + tid], sRed[256 + tid]);
}

// ================= e2: out = W2(256x256) @ mish(bn2(y)) + b2 =================
__global__ void __launch_bounds__(256) k_e2(const float* __restrict__ w2, const float* __restrict__ b2,
                                            const float* __restrict__ bn2g, const float* __restrict__ bn2b,
                                            float* __restrict__ out){
    extern __shared__ float smem2[];
    float* sM2  = smem2;            // 256 x 64
    float* sWT  = smem2 + 16384;    // 32 x 256 weight chunk
    float* sAB2 = smem2 + 24576;    // 512
    int tid = threadIdx.x, blk = blockIdx.x;
    int b = blk >> 8;
    int t0 = (blk & 255) << 6;
    {
        float s = g_stats_e[tid], q = g_stats_e[256 + tid];
        float m = s * (1.f/(float)BT);
        float v = q * (1.f/(float)BT) - m*m;
        float a = bn2g[tid] * rsqrtf(v + 1e-5f);
        sAB2[tid] = a; sAB2[256 + tid] = bn2b[tid] - m*a;
    }
    __syncthreads();
    #pragma unroll 4
    for (int i = 0; i < 16; i++){
        int e = tid + i*256;            // float4 idx in 256x64 tile
        int c = e >> 4, j4 = e & 15;
        float4 v = *(const float4*)&g_y[((size_t)(b*ECH + c))*TT + t0 + 4*j4];
        float a = sAB2[c], sh = sAB2[256+c];
        v.x = fast_mish(fmaf(a, v.x, sh));
        v.y = fast_mish(fmaf(a, v.y, sh));
        v.z = fast_mish(fmaf(a, v.z, sh));
        v.w = fast_mish(fmaf(a, v.w, sh));
        ((float4*)sM2)[e] = v;
    }
    int og = tid >> 4, tp = tid & 15;
    float4 acc[16];
    #pragma unroll
    for (int u = 0; u < 16; u++) acc[u] = make_float4(0.f,0.f,0.f,0.f);

    for (int kc = 0; kc < 8; kc++){
        __syncthreads();
        #pragma unroll
        for (int i = 0; i < 32; i++){
            int e = tid + i*256;
            int k = e >> 8, o = e & 255;
            sWT[e] = w2[o*256 + kc*32 + k];
        }
        __syncthreads();
        #pragma unroll 4
        for (int k = 0; k < 32; k++){
            float4 in = *(const float4*)(sM2 + (kc*32 + k)*64 + 4*tp);
            float w[16];
            *(float4*)&w[0]  = *(const float4*)(sWT + k*256 + 16*og);
            *(float4*)&w[4]  = *(const float4*)(sWT + k*256 + 16*og + 4);
            *(float4*)&w[8]  = *(const float4*)(sWT + k*256 + 16*og + 8);
            *(float4*)&w[12] = *(const float4*)(sWT + k*256 + 16*og + 12);
            #pragma unroll
            for (int u = 0; u < 16; u++){
                acc[u].x = fmaf(w[u], in.x, acc[u].x);
                acc[u].y = fmaf(w[u], in.y, acc[u].y);
                acc[u].z = fmaf(w[u], in.z, acc[u].z);
                acc[u].w = fmaf(w[u], in.w, acc[u].w);
            }
        }
    }
    #pragma unroll
    for (int u = 0; u < 16; u++){
        int o = 16*og + u;
        float bias = b2[o];
        float4 v = acc[u];
        v.x += bias; v.y += bias; v.z += bias; v.w += bias;
        *(float4*)&out[((size_t)(b*CLS + o))*TT + t0 + 4*tp] = v;
    }
}

// ================= launch =================
extern "C" void kernel_launch(void* const* d_in, const int* in_sizes, int n_in,
                              void* d_out, int out_size){
    const float* x       = (const float*)d_in[0];
    const float* start_w = (const float*)d_in[1];
    const float* start_b = (const float*)d_in[2];
    const float* gt_w    = (const float*)d_in[3];
    const float* gt_b    = (const float*)d_in[4];
    const float* gs_w    = (const float*)d_in[5];
    const float* gs_b    = (const float*)d_in[6];
    const float* res_w   = (const float*)d_in[7];
    const float* res_b   = (const float*)d_in[8];
    const float* bn_g    = (const float*)d_in[9];
    const float* bn_b    = (const float*)d_in[10];
    const float* bn1_g   = (const float*)d_in[11];
    const float* bn1_b   = (const float*)d_in[12];
    const float* e1_w    = (const float*)d_in[13];
    const float* e1_b    = (const float*)d_in[14];
    const float* bn2_g   = (const float*)d_in[15];
    const float* bn2_b   = (const float*)d_in[16];
    const float* e2_w    = (const float*)d_in[17];
    const float* e2_b    = (const float*)d_in[18];
    float* out = (float*)d_out;

    cudaFuncSetAttribute(k_layer, cudaFuncAttributeMaxDynamicSharedMemorySize, 13440*4);
    cudaFuncSetAttribute(k_e2,    cudaFuncAttributeMaxDynamicSharedMemorySize, 25088*4);

    k_start<<<BB*(TT/128), 256>>>(x, start_w, start_b);

    for (int L = 0; L < NL; L++){
        const float* gp = (L > 0) ? (bn_g + (size_t)(L-1)*RC) : bn_g;
        const float* bp = (L > 0) ? (bn_b + (size_t)(L-1)*RC) : bn_b;
        k_layer<<<BB*(TT/128), 256, 13440*4>>>(
            L,
            gt_w + (size_t)L*RC*RC*2, gt_b + L*RC,
            gs_w + (size_t)L*RC*RC*2, gs_b + L*RC,
            res_w + (size_t)L*RC*RC,  res_b + L*RC,
            gp, bp);
    }

    k_e1<<<BB*(TT/64), 256>>>(e1_w, e1_b, bn1_g, bn1_b);
    k_e2<<<BB*(TT/64), 256, 25088*4>>>(e2_w, e2_b, bn2_g, bn2_b, out);
}

// round 5
// speedup vs baseline: 1.3109x; 1.0874x over previous
#include <cuda_runtime.h>
#include <math.h>

#define BB 8
#define TT 16384
#define RC 32
#define CLS 256
#define ECH 256
#define NL 40
#define DILATION 1024
#define BT (BB*TT)
#define SLOT_BN1 39

typedef unsigned long long u64t;

__device__ __forceinline__ u64t splat2(float v){
    u64t d; asm("mov.b64 %0, {%1, %1};" : "=l"(d) : "f"(v)); return d;
}
__device__ __forceinline__ void ffma2(u64t &acc, u64t a, u64t b){
    asm("fma.rn.f32x2 %0, %1, %2, %0;" : "+l"(acc) : "l"(a), "l"(b));
}
__device__ __forceinline__ float2 unpack2(u64t d){
    float2 r; asm("mov.b64 {%0, %1}, %2;" : "=f"(r.x), "=f"(r.y) : "l"(d)); return r;
}

// -------- scratch (device globals; no allocation allowed) --------
__device__ float g_hA[BB*RC*TT];
__device__ float g_hB[BB*RC*TT];
__device__ float g_uA[BB*RC*TT];
__device__ float g_uB[BB*RC*TT];
__device__ float g_skip[BB*RC*TT];
__device__ float g_y[BB*ECH*TT];
__device__ float g_stats2[41*64];    // per-layer per-channel sum/sumsq (slot 39 = bn1)
__device__ float g_stats_e[512];     // bn2 stats

__device__ __forceinline__ float fast_tanh(float x){
    float e = __expf(fminf(2.f*x, 30.f));
    return __fdividef(e - 1.f, e + 1.f);
}
__device__ __forceinline__ float fast_sig(float x){
    return __fdividef(1.f, 1.f + __expf(fminf(-x, 30.f)));
}
__device__ __forceinline__ float fast_mish(float x){
    float e = __expf(fminf(x, 15.f));
    float p = 1.f + e;
    float p2 = p*p;
    float r = __fdividef(p2 - 1.f, p2 + 1.f);
    return (x > 15.f) ? x : x*r;
}

// ================= start conv: hA = W(32x256) @ shift1(x) + b; skip = 0; zero stats =================
__global__ void __launch_bounds__(256) k_start(const float* __restrict__ x,
                                               const float* __restrict__ sw,
                                               const float* __restrict__ sb){
    __shared__ float sX[32*128];
    __shared__ float sW[32*32];
    int tid = threadIdx.x, blk = blockIdx.x;
    int b = blk >> 7;            // grid = 8 * 128
    int t0 = (blk & 127) << 7;
    if (blk == 0){
        for (int i = tid; i < 41*64; i += 256) g_stats2[i] = 0.f;
        for (int i = tid; i < 512;  i += 256) g_stats_e[i] = 0.f;
    }
    int og = tid >> 6, tj = tid & 63;
    u64t acc[4][2];              // 4 output-pairs x 2 timesteps
    #pragma unroll
    for (int p = 0; p < 4; p++){ acc[p][0]=0ull; acc[p][1]=0ull; }

    for (int ch = 0; ch < 8; ch++){
        int base = ch*32;
        #pragma unroll
        for (int i = 0; i < 16; i++){
            int e = tid + i*256;
            int cc = e >> 7, j = e & 127;
            int gt = t0 + j - 1;
            sX[e] = (gt >= 0) ? x[((size_t)(b*CLS + base + cc))*TT + gt] : 0.f;
        }
        #pragma unroll
        for (int i = 0; i < 4; i++){
            int e = tid + i*256;
            int k = e >> 5, o = e & 31;
            sW[e] = sw[o*CLS + base + k];   // sW[k][o]
        }
        __syncthreads();
        #pragma unroll 8
        for (int k = 0; k < 32; k++){
            float2 in = *(const float2*)(sX + k*128 + 2*tj);
            u64t s0 = splat2(in.x), s1 = splat2(in.y);
            const u64t* wp = (const u64t*)(sW + k*32 + 8*og);
            #pragma unroll
            for (int p = 0; p < 4; p++){
                u64t w = wp[p];
                ffma2(acc[p][0], w, s0);
                ffma2(acc[p][1], w, s1);
            }
        }
        __syncthreads();
    }
    int t = t0 + 2*tj;
    #pragma unroll
    for (int p = 0; p < 4; p++){
        float2 v0 = unpack2(acc[p][0]);   // (out 2p, out 2p+1) at t
        float2 v1 = unpack2(acc[p][1]);   // at t+1
        int c0 = 8*og + 2*p, c1 = c0 + 1;
        float b0 = sb[c0], b1 = sb[c1];
        size_t i0 = ((size_t)(b*RC + c0))*TT + t;
        size_t i1 = ((size_t)(b*RC + c1))*TT + t;
        *(float2*)&g_hA[i0]   = make_float2(v0.x+b0, v1.x+b0);
        *(float2*)&g_hA[i1]   = make_float2(v0.y+b1, v1.y+b1);
        *(float2*)&g_skip[i0] = make_float2(0.f, 0.f);
        *(float2*)&g_skip[i1] = make_float2(0.f, 0.f);
    }
}

// ================= fused layer kernel: bn-apply(prev) + gates + skip + res conv + stats =================
// tile: 256 timesteps x 64 rows; 256 threads; 4 ts x 16 gate-outputs per thread
__global__ void __launch_bounds__(256, 2) k_layer(
    int L,
    const float* __restrict__ gtw, const float* __restrict__ gtb,
    const float* __restrict__ gsw, const float* __restrict__ gsb,
    const float* __restrict__ rw,  const float* __restrict__ rb,
    const float* __restrict__ gprev, const float* __restrict__ bprev)
{
    extern __shared__ float smem[];
    float* sIn  = smem;              // 64 x 256 = 16384
    float* sW   = smem + 16384;      // 64 x 64 gate weights (transposed, u=2c+s)
    float* sRW  = smem + 20480;      // 32 x 32 residual weights (transposed)
    float* sRed = smem + 21504;      // 64
    float* sAB  = smem + 21568;      // 64

    const bool first = (L == 0);
    const bool last  = (L == NL-1);
    const float* hIn  = (first || (L & 1)) ? g_hA : g_hB;
    float*       hOut = (L & 1) ? g_hB : g_hA;
    const float* uIn  = (L & 1) ? g_uA : g_uB;
    float*       uOut = (L & 1) ? g_uB : g_uA;
    const bool wH = (L >= 1) && !last;

    int tid = threadIdx.x, blk = blockIdx.x;
    int b = blk >> 6;                // grid = 8 * 64
    int t0 = (blk & 63) << 8;
    int og = tid >> 6, tj = tid & 63;
    int lane = tid & 31;

    if (tid < 32){
        float a = 0.f, sh = 0.f;
        if (!first){
            float s = g_stats2[(L-1)*64 + tid];
            float q = g_stats2[(L-1)*64 + 32 + tid];
            float m = s * (1.f/(float)BT);
            float v = q * (1.f/(float)BT) - m*m;
            a  = gprev[tid] * rsqrtf(v + 1e-5f);
            sh = bprev[tid] - m*a;
        }
        sAB[tid] = a; sAB[32+tid] = sh;
    }
    #pragma unroll
    for (int i = 0; i < 16; i++){
        int e = tid + i*256;
        int k = e >> 6, u = e & 63;
        int c = u >> 1, s = u & 1;
        int tap = (k < 32) ? 1 : 0;
        int kk = k & 31;
        const float* wsrc = s ? gsw : gtw;
        sW[e] = wsrc[(c*32 + kk)*2 + tap];
    }
    #pragma unroll
    for (int i = 0; i < 4; i++){
        int e = tid + i*256;
        sRW[e] = rw[(e & 31)*32 + (e >> 5)];
    }
    if (tid < 64) sRed[tid] = 0.f;
    __syncthreads();

    // staging with fused BN-apply of previous layer
    bool dvalid = (t0 >= DILATION);
    #pragma unroll
    for (int i = 0; i < 16; i++){
        int e = tid + i*256;            // float4 idx in 64x256 tile
        int r = e >> 6, j4 = e & 63;
        float4 v = make_float4(0.f,0.f,0.f,0.f);
        if (r < 32 || dvalid){
            int c = (r < 32) ? r : r - 32;
            size_t off = ((size_t)(b*RC + c))*TT + ((r < 32) ? t0 : t0 - DILATION) + 4*j4;
            v = *(const float4*)&hIn[off];
            if (!first){
                float a = sAB[c], sh = sAB[32+c];
                float4 u = *(const float4*)&uIn[off];
                v.x = fmaf(a, u.x, v.x) + sh;
                v.y = fmaf(a, u.y, v.y) + sh;
                v.z = fmaf(a, u.z, v.z) + sh;
                v.w = fmaf(a, u.w, v.w) + sh;
            }
            if (r < 32 && wH) *(float4*)&hOut[off] = v;
        }
        ((float4*)sIn)[e] = v;
    }
    __syncthreads();

    // gate GEMM: 64 k, 8 output-pairs, 4 timesteps (packed f32x2 over output pairs)
    u64t acc[8][4];
    #pragma unroll
    for (int p = 0; p < 8; p++){
        acc[p][0]=0ull; acc[p][1]=0ull; acc[p][2]=0ull; acc[p][3]=0ull;
    }
    const float* wbase = sW + 16*og;
    #pragma unroll 4
    for (int k = 0; k < 64; k++){
        float4 in4 = *(const float4*)(sIn + k*256 + 4*tj);
        u64t s0 = splat2(in4.x), s1 = splat2(in4.y), s2 = splat2(in4.z), s3 = splat2(in4.w);
        const u64t* wp = (const u64t*)(wbase + k*64);
        #pragma unroll
        for (int p = 0; p < 8; p++){
            u64t w = wp[p];
            ffma2(acc[p][0], w, s0);
            ffma2(acc[p][1], w, s1);
            ffma2(acc[p][2], w, s2);
            ffma2(acc[p][3], w, s3);
        }
    }
    __syncthreads();

    // epilogue: gates, skip accumulate, g into smem (or bn1 stats on last layer)
    size_t rowbase = ((size_t)(b*RC))*TT + t0 + 4*tj;
    #pragma unroll
    for (int p = 0; p < 8; p++){
        int c = 8*og + p;
        float tb = gtb[c], sb2 = gsb[c];
        float gv[4];
        #pragma unroll
        for (int ts = 0; ts < 4; ts++){
            float2 a2 = unpack2(acc[p][ts]);   // (tanh-pre, sig-pre)
            gv[ts] = fast_tanh(a2.x + tb) * fast_sig(a2.y + sb2);
        }
        size_t idx = rowbase + (size_t)c*TT;
        float4 sk = *(float4*)&g_skip[idx];
        sk.x += gv[0]; sk.y += gv[1]; sk.z += gv[2]; sk.w += gv[3];
        *(float4*)&g_skip[idx] = sk;
        if (!last){
            *(float4*)(sIn + c*256 + 4*tj) = make_float4(gv[0],gv[1],gv[2],gv[3]);
        } else {
            float s = sk.x+sk.y+sk.z+sk.w;
            float q = sk.x*sk.x+sk.y*sk.y+sk.z*sk.z+sk.w*sk.w;
            #pragma unroll
            for (int off = 16; off > 0; off >>= 1){
                s += __shfl_down_sync(0xffffffffu, s, off);
                q += __shfl_down_sync(0xffffffffu, q, off);
            }
            if (lane == 0){
                atomicAdd(&sRed[c],      s);
                atomicAdd(&sRed[32 + c], q);
            }
        }
    }
    if (last){
        __syncthreads();
        if (tid < 64) atomicAdd(&g_stats2[SLOT_BN1*64 + tid], sRed[tid]);
        return;
    }
    __syncthreads();

    // residual conv: 32 k, 4 output-pairs, 4 timesteps
    u64t racc[4][4];
    #pragma unroll
    for (int p = 0; p < 4; p++){
        racc[p][0]=0ull; racc[p][1]=0ull; racc[p][2]=0ull; racc[p][3]=0ull;
    }
    #pragma unroll 4
    for (int c = 0; c < 32; c++){
        float4 g4 = *(const float4*)(sIn + c*256 + 4*tj);
        u64t s0 = splat2(g4.x), s1 = splat2(g4.y), s2 = splat2(g4.z), s3 = splat2(g4.w);
        const u64t* wp = (const u64t*)(sRW + c*32 + 8*og);
        #pragma unroll
        for (int p = 0; p < 4; p++){
            u64t w = wp[p];
            ffma2(racc[p][0], w, s0);
            ffma2(racc[p][1], w, s1);
            ffma2(racc[p][2], w, s2);
            ffma2(racc[p][3], w, s3);
        }
    }
    #pragma unroll
    for (int p = 0; p < 4; p++){
        float2 v0 = unpack2(racc[p][0]);
        float2 v1 = unpack2(racc[p][1]);
        float2 v2 = unpack2(racc[p][2]);
        float2 v3 = unpack2(racc[p][3]);
        int o0 = 8*og + 2*p, o1 = o0 + 1;
        float bias0 = rb[o0], bias1 = rb[o1];
        float4 u0 = make_float4(v0.x+bias0, v1.x+bias0, v2.x+bias0, v3.x+bias0);
        float4 u1 = make_float4(v0.y+bias1, v1.y+bias1, v2.y+bias1, v3.y+bias1);
        *(float4*)&uOut[rowbase + (size_t)o0*TT] = u0;
        *(float4*)&uOut[rowbase + (size_t)o1*TT] = u1;
        float s0s = u0.x+u0.y+u0.z+u0.w;
        float q0s = u0.x*u0.x+u0.y*u0.y+u0.z*u0.z+u0.w*u0.w;
        float s1s = u1.x+u1.y+u1.z+u1.w;
        float q1s = u1.x*u1.x+u1.y*u1.y+u1.z*u1.z+u1.w*u1.w;
        #pragma unroll
        for (int off = 16; off > 0; off >>= 1){
            s0s += __shfl_down_sync(0xffffffffu, s0s, off);
            q0s += __shfl_down_sync(0xffffffffu, q0s, off);
            s1s += __shfl_down_sync(0xffffffffu, s1s, off);
            q1s += __shfl_down_sync(0xffffffffu, q1s, off);
        }
        if (lane == 0){
            atomicAdd(&sRed[o0],      s0s);
            atomicAdd(&sRed[32 + o0], q0s);
            atomicAdd(&sRed[o1],      s1s);
            atomicAdd(&sRed[32 + o1], q1s);
        }
    }
    __syncthreads();
    if (tid < 64) atomicAdd(&g_stats2[L*64 + tid], sRed[tid]);
}

// ================= e1: y = W1(256x32) @ mish(bn1(skip)) + b1, accumulate bn2 stats =================
__global__ void __launch_bounds__(256) k_e1(const float* __restrict__ w1, const float* __restrict__ b1,
                                            const float* __restrict__ bn1g, const float* __restrict__ bn1b){
    __shared__ float sM[32*64];
    __shared__ float sWT[32*256];
    __shared__ float sRed[512];
    __shared__ float sAB[64];
    int tid = threadIdx.x, blk = blockIdx.x;
    int b = blk >> 8;               // grid = 8 * 256
    int t0 = (blk & 255) << 6;
    if (tid < 32){
        float s = g_stats2[SLOT_BN1*64 + tid];
        float q = g_stats2[SLOT_BN1*64 + 32 + tid];
        float m = s * (1.f/(float)BT);
        float v = q * (1.f/(float)BT) - m*m;
        float a = bn1g[tid] * rsqrtf(v + 1e-5f);
        sAB[tid] = a; sAB[32+tid] = bn1b[tid] - m*a;
    }
    #pragma unroll
    for (int i = 0; i < 32; i++){
        int e = tid + i*256;
        int k = e >> 8, o = e & 255;
        sWT[e] = w1[o*32 + k];
    }
    sRed[tid] = 0.f; sRed[256 + tid] = 0.f;
    __syncthreads();
    #pragma unroll
    for (int i = 0; i < 2; i++){
        int e = tid + i*256;
        int c = e >> 4, j4 = e & 15;
        float4 v = *(const float4*)&g_skip[((size_t)(b*RC + c))*TT + t0 + 4*j4];
        float a = sAB[c], sh = sAB[32+c];
        v.x = fast_mish(fmaf(a, v.x, sh));
        v.y = fast_mish(fmaf(a, v.y, sh));
        v.z = fast_mish(fmaf(a, v.z, sh));
        v.w = fast_mish(fmaf(a, v.w, sh));
        ((float4*)sM)[e] = v;
    }
    __syncthreads();

    int og = tid >> 4, tp = tid & 15;
    u64t acc[8][4];
    #pragma unroll
    for (int p = 0; p < 8; p++){
        acc[p][0]=0ull; acc[p][1]=0ull; acc[p][2]=0ull; acc[p][3]=0ull;
    }
    #pragma unroll 4
    for (int k = 0; k < 32; k++){
        float4 in = *(const float4*)(sM + k*64 + 4*tp);
        u64t s0 = splat2(in.x), s1 = splat2(in.y), s2 = splat2(in.z), s3 = splat2(in.w);
        const u64t* wp = (const u64t*)(sWT + k*256 + 16*og);
        #pragma unroll
        for (int p = 0; p < 8; p++){
            u64t w = wp[p];
            ffma2(acc[p][0], w, s0);
            ffma2(acc[p][1], w, s1);
            ffma2(acc[p][2], w, s2);
            ffma2(acc[p][3], w, s3);
        }
    }
    int lane16 = tid & 15;
    #pragma unroll
    for (int p = 0; p < 8; p++){
        float2 v0 = unpack2(acc[p][0]);
        float2 v1 = unpack2(acc[p][1]);
        float2 v2 = unpack2(acc[p][2]);
        float2 v3 = unpack2(acc[p][3]);
        int o0 = 16*og + 2*p, o1 = o0 + 1;
        float bias0 = b1[o0], bias1 = b1[o1];
        float4 y0 = make_float4(v0.x+bias0, v1.x+bias0, v2.x+bias0, v3.x+bias0);
        float4 y1 = make_float4(v0.y+bias1, v1.y+bias1, v2.y+bias1, v3.y+bias1);
        *(float4*)&g_y[((size_t)(b*ECH + o0))*TT + t0 + 4*tp] = y0;
        *(float4*)&g_y[((size_t)(b*ECH + o1))*TT + t0 + 4*tp] = y1;
        float s0s = y0.x+y0.y+y0.z+y0.w, q0s = y0.x*y0.x+y0.y*y0.y+y0.z*y0.z+y0.w*y0.w;
        float s1s = y1.x+y1.y+y1.z+y1.w, q1s = y1.x*y1.x+y1.y*y1.y+y1.z*y1.z+y1.w*y1.w;
        #pragma unroll
        for (int off = 8; off > 0; off >>= 1){
            s0s += __shfl_xor_sync(0xffffffffu, s0s, off);
            q0s += __shfl_xor_sync(0xffffffffu, q0s, off);
            s1s += __shfl_xor_sync(0xffffffffu, s1s, off);
            q1s += __shfl_xor_sync(0xffffffffu, q1s, off);
        }
        if (lane16 == 0){
            atomicAdd(&sRed[o0],       s0s);
            atomicAdd(&sRed[256 + o0], q0s);
            atomicAdd(&sRed[o1],       s1s);
            atomicAdd(&sRed[256 + o1], q1s);
        }
    }
    __syncthreads();
    atomicAdd(&g_stats_e[tid],       sRed[tid]);
    atomicAdd(&g_stats_e[256 + tid], sRed[256 + tid]);
}

// ================= e2: out = W2(256x256) @ mish(bn2(y)) + b2 =================
__global__ void __launch_bounds__(256, 2) k_e2(const float* __restrict__ w2, const float* __restrict__ b2,
                                               const float* __restrict__ bn2g, const float* __restrict__ bn2b,
                                               float* __restrict__ out){
    extern __shared__ float smem2[];
    float* sM2  = smem2;            // 256 x 64
    float* sWT  = smem2 + 16384;    // 32 x 256 weight chunk
    float* sAB2 = smem2 + 24576;    // 512
    int tid = threadIdx.x, blk = blockIdx.x;
    int b = blk >> 8;
    int t0 = (blk & 255) << 6;
    {
        float s = g_stats_e[tid], q = g_stats_e[256 + tid];
        float m = s * (1.f/(float)BT);
        float v = q * (1.f/(float)BT) - m*m;
        float a = bn2g[tid] * rsqrtf(v + 1e-5f);
        sAB2[tid] = a; sAB2[256 + tid] = bn2b[tid] - m*a;
    }
    __syncthreads();
    #pragma unroll 4
    for (int i = 0; i < 16; i++){
        int e = tid + i*256;
        int c = e >> 4, j4 = e & 15;
        float4 v = *(const float4*)&g_y[((size_t)(b*ECH + c))*TT + t0 + 4*j4];
        float a = sAB2[c], sh = sAB2[256+c];
        v.x = fast_mish(fmaf(a, v.x, sh));
        v.y = fast_mish(fmaf(a, v.y, sh));
        v.z = fast_mish(fmaf(a, v.z, sh));
        v.w = fast_mish(fmaf(a, v.w, sh));
        ((float4*)sM2)[e] = v;
    }
    int og = tid >> 4, tp = tid & 15;
    u64t acc[8][4];
    #pragma unroll
    for (int p = 0; p < 8; p++){
        acc[p][0]=0ull; acc[p][1]=0ull; acc[p][2]=0ull; acc[p][3]=0ull;
    }

    for (int kc = 0; kc < 8; kc++){
        __syncthreads();
        #pragma unroll
        for (int i = 0; i < 32; i++){
            int e = tid + i*256;
            int k = e >> 8, o = e & 255;
            sWT[e] = w2[o*256 + kc*32 + k];
        }
        __syncthreads();
        #pragma unroll 4
        for (int k = 0; k < 32; k++){
            float4 in = *(const float4*)(sM2 + (kc*32 + k)*64 + 4*tp);
            u64t s0 = splat2(in.x), s1 = splat2(in.y), s2 = splat2(in.z), s3 = splat2(in.w);
            const u64t* wp = (const u64t*)(sWT + k*256 + 16*og);
            #pragma unroll
            for (int p = 0; p < 8; p++){
                u64t w = wp[p];
                ffma2(acc[p][0], w, s0);
                ffma2(acc[p][1], w, s1);
                ffma2(acc[p][2], w, s2);
                ffma2(acc[p][3], w, s3);
            }
        }
    }
    #pragma unroll
    for (int p = 0; p < 8; p++){
        float2 v0 = unpack2(acc[p][0]);
        float2 v1 = unpack2(acc[p][1]);
        float2 v2 = unpack2(acc[p][2]);
        float2 v3 = unpack2(acc[p][3]);
        int o0 = 16*og + 2*p, o1 = o0 + 1;
        float bias0 = b2[o0], bias1 = b2[o1];
        *(float4*)&out[((size_t)(b*CLS + o0))*TT + t0 + 4*tp] =
            make_float4(v0.x+bias0, v1.x+bias0, v2.x+bias0, v3.x+bias0);
        *(float4*)&out[((size_t)(b*CLS + o1))*TT + t0 + 4*tp] =
            make_float4(v0.y+bias1, v1.y+bias1, v2.y+bias1, v3.y+bias1);
    }
}

// ================= launch =================
extern "C" void kernel_launch(void* const* d_in, const int* in_sizes, int n_in,
                              void* d_out, int out_size){
    const float* x       = (const float*)d_in[0];
    const float* start_w = (const float*)d_in[1];
    const float* start_b = (const float*)d_in[2];
    const float* gt_w    = (const float*)d_in[3];
    const float* gt_b    = (const float*)d_in[4];
    const float* gs_w    = (const float*)d_in[5];
    const float* gs_b    = (const float*)d_in[6];
    const float* res_w   = (const float*)d_in[7];
    const float* res_b   = (const float*)d_in[8];
    const float* bn_g    = (const float*)d_in[9];
    const float* bn_b    = (const float*)d_in[10];
    const float* bn1_g   = (const float*)d_in[11];
    const float* bn1_b   = (const float*)d_in[12];
    const float* e1_w    = (const float*)d_in[13];
    const float* e1_b    = (const float*)d_in[14];
    const float* bn2_g   = (const float*)d_in[15];
    const float* bn2_b   = (const float*)d_in[16];
    const float* e2_w    = (const float*)d_in[17];
    const float* e2_b    = (const float*)d_in[18];
    float* out = (float*)d_out;

    cudaFuncSetAttribute(k_layer, cudaFuncAttributeMaxDynamicSharedMemorySize, 21632*4);
    cudaFuncSetAttribute(k_e2,    cudaFuncAttributeMaxDynamicSharedMemorySize, 25088*4);

    k_start<<<BB*(TT/128), 256>>>(x, start_w, start_b);

    for (int L = 0; L < NL; L++){
        const float* gp = (L > 0) ? (bn_g + (size_t)(L-1)*RC) : bn_g;
        const float* bp = (L > 0) ? (bn_b + (size_t)(L-1)*RC) : bn_b;
        k_layer<<<BB*(TT/256), 256, 21632*4>>>(
            L,
            gt_w + (size_t)L*RC*RC*2, gt_b + L*RC,
            gs_w + (size_t)L*RC*RC*2, gs_b + L*RC,
            res_w + (size_t)L*RC*RC,  res_b + L*RC,
            gp, bp);
    }

    k_e1<<<BB*(TT/64), 256>>>(e1_w, e1_b, bn1_g, bn1_b);
    k_e2<<<BB*(TT/64), 256, 25088*4>>>(e2_w, e2_b, bn2_g, bn2_b, out);
}